// round 8
// baseline (speedup 1.0000x reference)
#include <cuda_runtime.h>
#include <math.h>

#define WIDTH  128
#define HEIGHT 128
#define NEARP  0.1f
#define FARP   10.0f
#define EPSV   1e-8f

#define THREADS   512
#define PX_BLK    64     // pixels per block (half a row)
#define PXT       32     // pixel-threads; each handles 2 pixels (p, p+32)
#define SLICES    16     // warps per block

__device__ __forceinline__ void compute_mvp(const float* cf, const float* cc,
                                            const float* tt, const float* rt,
                                            float* MVP) {
    float r0 = rt[0], r1 = rt[1], r2 = rt[2];
    float theta = sqrtf(r0 * r0 + r1 * r1 + r2 * r2 + 1e-12f);
    float k0 = r0 / theta, k1 = r1 / theta, k2 = r2 / theta;
    float st = sinf(theta), ctv = cosf(theta);
    float K[9] = { 0.f, -k2,  k1,
                   k2,  0.f, -k0,
                  -k1,  k0,  0.f };
    float KK[9];
    for (int i = 0; i < 3; i++)
        for (int j = 0; j < 3; j++) {
            float s = 0.f;
            for (int k = 0; k < 3; k++) s += K[i * 3 + k] * K[k * 3 + j];
            KK[i * 3 + j] = s;
        }
    float R[9];
    for (int i = 0; i < 3; i++)
        for (int j = 0; j < 3; j++)
            R[i * 3 + j] = (i == j ? 1.f : 0.f) + st * K[i * 3 + j] + (1.f - ctv) * KK[i * 3 + j];

    float Vw[16];
    for (int i = 0; i < 3; i++) {
        for (int j = 0; j < 3; j++) Vw[i * 4 + j] = R[j * 3 + i];
        Vw[i * 4 + 3] = 0.f;
    }
    Vw[12] = tt[0]; Vw[13] = tt[1]; Vw[14] = tt[2]; Vw[15] = 1.f;

    float fav = 0.5f * (cf[0] + cf[1]);
    float s = NEARP / fav;
    float right  = ((float)WIDTH - (cc[0] + 0.5f)) * s;
    float left   = -(cc[0] + 0.5f) * s;
    float top    = (cc[1] + 0.5f) * s;
    float bottom = -((float)HEIGHT - cc[1] + 0.5f) * s;
    float P[16];
    for (int i = 0; i < 16; i++) P[i] = 0.f;
    P[0]  = 2.f * NEARP / (right - left);
    P[5]  = 2.f * NEARP / (top - bottom);
    P[8]  = (right + left) / (right - left);
    P[9]  = (top + bottom) / (top - bottom);
    P[10] = -(FARP + NEARP) / (FARP - NEARP);
    P[11] = -1.f;
    P[14] = -2.f * FARP * NEARP / (FARP - NEARP);

    for (int i = 0; i < 4; i++)
        for (int j = 0; j < 4; j++) {
            float sij = 0.f;
            for (int k = 0; k < 4; k++) sij += Vw[i * 4 + k] * P[k * 4 + j];
            MVP[i * 4 + j] = sij;
        }
}

// Fused renderer: setup -> quantized-bbox compaction -> software-pipelined
// balanced eval over survivors -> (z,idx)-key argmin merge -> shade.
// Survivor eval arithmetic is bit-identical to the reference.
extern "C" __global__ void __launch_bounds__(THREADS, 2)
render_kernel(const float* __restrict__ v,
              const float* __restrict__ vc,
              const int*   __restrict__ f,
              const float* __restrict__ bg,
              const float* __restrict__ cf,
              const float* __restrict__ cc,
              const float* __restrict__ ct,
              const float* __restrict__ crt,
              float* __restrict__ out,
              int Vn, int Fn) {
    extern __shared__ char smem_raw[];
    float4*   s_triA = (float4*)smem_raw;                             // Fn
    float4*   s_triB = (float4*)((char*)s_triA + (size_t)Fn * 16);    // Fn
    float2*   s_triC = (float2*)((char*)s_triB + (size_t)Fn * 16);    // Fn
    unsigned* s_bbq  = (unsigned*)((char*)s_triC + (size_t)Fn * 8);   // Fn (u8x4 bbox)
    float4*   s_vert = (float4*)((char*)s_bbq + (size_t)Fn * 4);      // Vn (x,y,z, ±invw)
    unsigned long long* s_red =
        (unsigned long long*)((char*)s_vert + (size_t)Vn * 16);       // SLICES*PX_BLK
    int* s_list = (int*)((char*)s_red + (size_t)SLICES * PX_BLK * 8); // Fn
    __shared__ float MVP[16];
    __shared__ int s_cnt;

    int tid = threadIdx.x;
    int b   = blockIdx.y;

    if (tid == 0) { compute_mvp(cf, cc, ct, crt, MVP); s_cnt = 0; }
    __syncthreads();

    // ---- vertex transform (validity folded into sign of .w) ----
    for (int i = tid; i < Vn; i += THREADS) {
        const float* vp = v + ((size_t)b * Vn + i) * 3;
        float X = vp[0], Y = vp[1], Z = vp[2];
        float c0 = X * MVP[0] + Y * MVP[4] + Z * MVP[8]  + MVP[12];
        float c1 = X * MVP[1] + Y * MVP[5] + Z * MVP[9]  + MVP[13];
        float c2 = X * MVP[2] + Y * MVP[6] + Z * MVP[10] + MVP[14];
        float c3 = X * MVP[3] + Y * MVP[7] + Z * MVP[11] + MVP[15];
        bool valid = c3 > EPSV;
        float ws = valid ? c3 : 1.f;
        float nx = c0 / ws, ny = c1 / ws, nz = c2 / ws;
        float xs = (nx * 0.5f + 0.5f) * (float)WIDTH;
        float ys = (0.5f - ny * 0.5f) * (float)HEIGHT;
        float iw = 1.f / ws;                       // > 0 always
        s_vert[i] = make_float4(xs, ys, nz, valid ? iw : -1.f);
    }
    __syncthreads();

    // ---- triangle setup + conservative quantized bbox ----
    for (int t = tid; t < Fn; t += THREADS) {
        int i0 = f[t * 3 + 0], i1 = f[t * 3 + 1], i2 = f[t * 3 + 2];
        float4 A  = s_vert[i0];
        float4 Bv = s_vert[i1];
        float4 C  = s_vert[i2];
        float area = (Bv.x - A.x) * (C.y - A.y) - (Bv.y - A.y) * (C.x - A.x);
        bool va = fabsf(area) > EPSV;
        float area_safe = va ? area : 1.f;
        float inva = 1.f / area_safe;
        bool valid = (A.w > 0.f) && (Bv.w > 0.f) && (C.w > 0.f) && va;
        float za = A.z, zb = Bv.z, zc = C.z;
        if (!valid) {
            float qn = __int_as_float(0x7FC00000);   // NaN -> never selected
            za = qn; zb = qn; zc = qn;
        }
        // conservative u8 bbox: floor mins, ceil maxes, clamp [0,255]
        int xmn = __float2int_rd(fminf(A.x, fminf(Bv.x, C.x)));
        int xmx = __float2int_ru(fmaxf(A.x, fmaxf(Bv.x, C.x)));
        int ymn = __float2int_rd(fminf(A.y, fminf(Bv.y, C.y)));
        int ymx = __float2int_ru(fmaxf(A.y, fmaxf(Bv.y, C.y)));
        xmn = min(max(xmn, 0), 255); xmx = min(max(xmx, 0), 255);
        ymn = min(max(ymn, 0), 255); ymx = min(max(ymx, 0), 255);
        s_bbq[t]  = (unsigned)xmn | ((unsigned)xmx << 8) |
                    ((unsigned)ymn << 16) | ((unsigned)ymx << 24);
        s_triA[t] = make_float4(A.x, A.y, Bv.x, Bv.y);
        s_triB[t] = make_float4(C.x, C.y, za, zb);
        s_triC[t] = make_float2(zc, inva);
    }
    __syncthreads();

    // ---- bbox compaction for this block's (row, x-range) ----
    int base  = blockIdx.x * PX_BLK;
    int row   = base >> 7;                 // WIDTH==128; one row per block
    int xlo_i = base & (WIDTH - 1);
    int xhi_i = xlo_i + (PX_BLK - 1);
    float y   = (float)row + 0.5f;
    float xlo = (float)xlo_i + 0.5f;

    for (int t = tid; t < Fn; t += THREADS) {
        unsigned q = s_bbq[t];
        int xmn = q & 255, xmx = (q >> 8) & 255;
        int ymn = (q >> 16) & 255, ymx = q >> 24;
        bool hit = (ymn <= row) && (ymx > row) && (xmn <= xhi_i) && (xmx > xlo_i);
        if (hit) {
            int slot = atomicAdd(&s_cnt, 1);   // unordered ok: key-min is order-invariant
            s_list[slot] = t;
        }
    }
    __syncthreads();
    int n = s_cnt;

    // ---- software-pipelined balanced eval over survivors ----
    int pxl   = tid & (PXT - 1);          // lane 0..31
    int slice = tid / PXT;                // warp 0..15
    float x0  = xlo + (float)pxl;
    float x1  = x0 + (float)PXT;

    float bz0 = INFINITY, bz1 = INFINITY;
    int   bi0 = -1,       bi1 = -1;

    int i = slice;
    int t = (i < n) ? s_list[i] : 0;
    float4 TA = s_triA[t];
    float4 TB = s_triB[t];
    float2 TC = s_triC[t];

    while (i < n) {
        // prefetch next iteration's record
        int inext = i + SLICES;
        int tn = (inext < n) ? s_list[inext] : 0;
        float4 TAn = s_triA[tn];
        float4 TBn = s_triB[tn];
        float2 TCn = s_triC[tn];

        float dCBx = TB.x - TA.z, dCBy = TB.y - TA.w;
        float dACx = TA.x - TB.x, dACy = TA.y - TB.y;
        float dBAx = TA.z - TA.x, dBAy = TA.w - TA.y;
        float ymB = y - TA.w, ymC = y - TB.y, ymA = y - TA.y;
        float inva = TC.y;

        {   // pixel 0
            float w0 = dCBx * ymB - dCBy * (x0 - TA.z);
            float w1 = dACx * ymC - dACy * (x0 - TB.x);
            float w2 = dBAx * ymA - dBAy * (x0 - TA.x);
            float b0 = w0 * inva, b1 = w1 * inva, b2 = w2 * inva;
            float z = b0 * TB.z + b1 * TB.w + b2 * TC.x;   // NaN if invalid
            bool inside = (b0 >= 0.f) && (b1 >= 0.f) && (b2 >= 0.f) &&
                          (z >= -1.f) && (z <= 1.f);
            if (inside && z < bz0) { bz0 = z; bi0 = t; }
        }
        {   // pixel 1
            float w0 = dCBx * ymB - dCBy * (x1 - TA.z);
            float w1 = dACx * ymC - dACy * (x1 - TB.x);
            float w2 = dBAx * ymA - dBAy * (x1 - TA.x);
            float b0 = w0 * inva, b1 = w1 * inva, b2 = w2 * inva;
            float z = b0 * TB.z + b1 * TB.w + b2 * TC.x;
            bool inside = (b0 >= 0.f) && (b1 >= 0.f) && (b2 >= 0.f) &&
                          (z >= -1.f) && (z <= 1.f);
            if (inside && z < bz1) { bz1 = z; bi1 = t; }
        }

        TA = TAn; TB = TBn; TC = TCn; t = tn; i = inext;
    }

    // pack (orderable z, tri idx): lexicographic min == argmin first-index
    unsigned long long k0 = ~0ull, k1 = ~0ull;
    if (bi0 >= 0) {
        unsigned zu = __float_as_uint(bz0);
        zu = (zu & 0x80000000u) ? ~zu : (zu | 0x80000000u);
        k0 = ((unsigned long long)zu << 32) | (unsigned)bi0;
    }
    if (bi1 >= 0) {
        unsigned zu = __float_as_uint(bz1);
        zu = (zu & 0x80000000u) ? ~zu : (zu | 0x80000000u);
        k1 = ((unsigned long long)zu << 32) | (unsigned)bi1;
    }
    s_red[slice * PX_BLK + pxl]       = k0;
    s_red[slice * PX_BLK + pxl + PXT] = k1;
    __syncthreads();

    // ---- merge + shade (first PX_BLK threads) ----
    if (tid < PX_BLK) {
        int p = tid;
        unsigned long long best = s_red[p];
#pragma unroll
        for (int sl = 1; sl < SLICES; sl++)
            best = min(best, s_red[sl * PX_BLK + p]);

        int pg = base + p;
        float xp = (float)(pg & (WIDTH - 1)) + 0.5f;
        float yp = (float)(pg >> 7) + 0.5f;
        float cr, cg, cb;
        if ((unsigned)(best >> 32) == 0xFFFFFFFFu) {
            cr = bg[0]; cg = bg[1]; cb = bg[2];
        } else {
            int tt = (int)(unsigned)best;
            float4 A4 = s_triA[tt];
            float4 B4 = s_triB[tt];
            float2 C2 = s_triC[tt];
            float dCBx = B4.x - A4.z, dCBy = B4.y - A4.w;
            float dACx = A4.x - B4.x, dACy = A4.y - B4.y;
            float dBAx = A4.z - A4.x, dBAy = A4.w - A4.y;
            float w0 = dCBx * (yp - A4.w) - dCBy * (xp - A4.z);
            float w1 = dACx * (yp - B4.y) - dACy * (xp - B4.x);
            float w2 = dBAx * (yp - A4.y) - dBAy * (xp - A4.x);
            float inva = C2.y;
            float b0 = w0 * inva, b1 = w1 * inva, b2 = w2 * inva;
            int i0 = f[tt * 3 + 0], i1 = f[tt * 3 + 1], i2 = f[tt * 3 + 2];
            float q0 = b0 * s_vert[i0].w;   // selected tri => all verts valid => +invw
            float q1 = b1 * s_vert[i1].w;
            float q2 = b2 * s_vert[i2].w;
            float den = q0 + q1 + q2;
            if (!(fabsf(den) > EPSV)) den = 1.f;
            cr = (q0 * vc[i0 * 3 + 0] + q1 * vc[i1 * 3 + 0] + q2 * vc[i2 * 3 + 0]) / den;
            cg = (q0 * vc[i0 * 3 + 1] + q1 * vc[i1 * 3 + 1] + q2 * vc[i2 * 3 + 1]) / den;
            cb = (q0 * vc[i0 * 3 + 2] + q1 * vc[i1 * 3 + 2] + q2 * vc[i2 * 3 + 2]) / den;
        }
        float* op = out + ((size_t)b * HEIGHT * WIDTH + pg) * 3;
        op[0] = cr; op[1] = cg; op[2] = cb;
    }
}

extern "C" void kernel_launch(void* const* d_in, const int* in_sizes, int n_in,
                              void* d_out, int out_size) {
    const float* v   = (const float*)d_in[0];
    const float* vc  = (const float*)d_in[1];
    const int*   f   = (const int*)d_in[2];
    const float* bg  = (const float*)d_in[3];
    const float* cf  = (const float*)d_in[4];
    const float* cc  = (const float*)d_in[5];
    const float* ct  = (const float*)d_in[6];
    const float* crt = (const float*)d_in[7];

    int Vn = in_sizes[1] / 3;
    int Fn = in_sizes[2] / 3;
    int Bn = in_sizes[0] / (3 * Vn);

    size_t smem = (size_t)Fn * 44 + (size_t)Vn * 16 +
                  (size_t)SLICES * PX_BLK * 8 + (size_t)Fn * 4;
    static int smem_set = 0;
    if (!smem_set) {
        cudaFuncSetAttribute(render_kernel,
                             cudaFuncAttributeMaxDynamicSharedMemorySize,
                             (int)smem);
        smem_set = 1;
    }
    dim3 grid(HEIGHT * WIDTH / PX_BLK, Bn);
    render_kernel<<<grid, THREADS, smem>>>(v, vc, f, bg, cf, cc, ct, crt,
                                           (float*)d_out, Vn, Fn);
}